// round 7
// baseline (speedup 1.0000x reference)
#include <cuda_runtime.h>
#include <cstdint>

// PointPillars scatter, inverted as index-map + tiled-transpose gather.
// B=4, C=64, H=512, W=512, P read from in_sizes.
//
// Init-free map: g_map holds (pid+1), 0 = empty. Zero-initialized at module
// load; the gather resets consumed cells inline, so every graph replay
// starts from a clean map (scatter -> gather stream ordering).
#define B_ 4
#define C_ 64
#define H_ 512
#define W_ 512
#define HW_ (H_ * W_)        // 262144 = 2^18
#define BHW_ (B_ * HW_)      // 1048576

#define TILE_ 64             // cells per gather block
#define GTHREADS_ 512

__device__ int g_map[BHW_];  // zero-initialized at load; 0 = empty

// ---------------------------------------------------------------------------
// Kernel 1: scatter (pid+1) per pillar. atomicMax => highest pillar index
// wins == the reference's sequential last-write-wins.
__global__ void __launch_bounds__(512) k_scatter_idx(const int* __restrict__ coords, int P) {
    int p = blockIdx.x * blockDim.x + threadIdx.x;
    if (p >= P) return;
    int4 c = __ldcs(reinterpret_cast<const int4*>(coords) + p);  // [b, z, y, x]
    int b = c.x, y = c.z, x = c.w;
    if ((unsigned)y < H_ && (unsigned)x < W_) {
        atomicMax(&g_map[(b * H_ + y) * W_ + x], p + 1);
    }
}

// ---------------------------------------------------------------------------
// Kernel 2: tiled gather. Block = 512 threads, 64 consecutive BEV cells.
// Phase A: cooperative coalesced read of occupied feature rows into smem
//          (8 threads per cell; each row = 2 x 128B lines since rows are
//          256B-aligned). Empty cells are zero-filled in smem.
// Phase B: transposed smem read, STG.128 stores along sp — per warp each
//          channel writes a contiguous 256B segment. Full lines everywhere.
__global__ void __launch_bounds__(GTHREADS_) k_gather(const float* __restrict__ feat,
                                                      float* __restrict__ out) {
    __shared__ int   s_pid[TILE_];
    __shared__ float s_f[TILE_][C_ + 1];   // stride 65 breaks bank conflicts

    const int tid = threadIdx.x;
    const int s0  = blockIdx.x * TILE_;    // first global cell of this tile

    // --- map read + inline self-clean (one thread per cell) ---
    if (tid < TILE_) {
        int v = g_map[s0 + tid];
        if (v > 0) g_map[s0 + tid] = 0;    // reset for next graph replay
        s_pid[tid] = v;
    }
    __syncthreads();

    // --- Phase A: load feature rows into smem (transposing write) ---
    {
        int cell = tid >> 3;               // 0..63
        int t    = tid & 7;                // 0..7: which 16B of each 128B line
        int v    = s_pid[cell];
        float4 a, b;
        if (v > 0) {
            const float4* fp = reinterpret_cast<const float4*>(feat) + (size_t)(v - 1) * 16;
            a = __ldcs(fp + t);            // bytes [t*16, t*16+16) of line 0
            b = __ldcs(fp + t + 8);        // bytes [t*16, ...) of line 1
        } else {
            a = make_float4(0.f, 0.f, 0.f, 0.f);
            b = a;
        }
        int c0 = 4 * t;                    // channels 4t..4t+3
        s_f[cell][c0 + 0] = a.x;  s_f[cell][c0 + 1] = a.y;
        s_f[cell][c0 + 2] = a.z;  s_f[cell][c0 + 3] = a.w;
        int c1 = 4 * (t + 8);              // channels 4t+32..4t+35
        s_f[cell][c1 + 0] = b.x;  s_f[cell][c1 + 1] = b.y;
        s_f[cell][c1 + 2] = b.z;  s_f[cell][c1 + 3] = b.w;
    }
    __syncthreads();

    // --- Phase B: transposed read, vectorized stores along sp ---
    {
        int c = tid >> 3;                  // channel 0..63
        int g = tid & 7;                   // cell-group: cells [8g, 8g+8)
        float v0 = s_f[8 * g + 0][c], v1 = s_f[8 * g + 1][c];
        float v2 = s_f[8 * g + 2][c], v3 = s_f[8 * g + 3][c];
        float v4 = s_f[8 * g + 4][c], v5 = s_f[8 * g + 5][c];
        float v6 = s_f[8 * g + 6][c], v7 = s_f[8 * g + 7][c];

        int b  = s0 >> 18;                 // batch (tile never crosses batch)
        int sp = s0 & (HW_ - 1);
        float4* op = reinterpret_cast<float4*>(
            out + (size_t)b * (C_ * HW_) + (size_t)c * HW_ + sp + 8 * g);
        __stcs(op + 0, make_float4(v0, v1, v2, v3));
        __stcs(op + 1, make_float4(v4, v5, v6, v7));
    }
}

// ---------------------------------------------------------------------------
extern "C" void kernel_launch(void* const* d_in, const int* in_sizes, int n_in,
                              void* d_out, int out_size) {
    const float* feat   = (const float*)d_in[0];   // [P, C] float32
    const int*   coords = (const int*)d_in[1];     // [P, 4] int32
    int P = in_sizes[1] / 4;

    k_scatter_idx<<<(P + 511) / 512, 512>>>(coords, P);
    k_gather<<<BHW_ / TILE_, GTHREADS_>>>(feat, (float*)d_out);
}

// round 8
// speedup vs baseline: 1.4533x; 1.4533x over previous
#include <cuda_runtime.h>
#include <cstdint>

// PointPillars scatter, inverted as index-map + gather.
// B=4, C=64, H=512, W=512, P read from in_sizes.
//
// Init-free map: g_map holds (pid+1), 0 = empty. Zero-initialized at module
// load; gather self-cleans consumed cells so every graph replay starts from
// a clean map (scatter -> gather stream ordering guarantees the reset lands
// before the next replay's atomics).
//
// Cache policy: feat (100 MB) fits in L2 (~126 MB) and is re-read every
// graph replay -> default (cache-all) loads so it stays L2-resident across
// replays. The 256 MB output is write-once streaming -> __stcs so it does
// not evict feat. No __syncthreads anywhere in the gather: every warp's
// random reads overlap freely with its stores (round-7 showed barrier
// coupling collapses MLP).
#define B_ 4
#define C_ 64
#define H_ 512
#define W_ 512
#define HW_ (H_ * W_)        // 262144 = 2^18
#define BHW_ (B_ * HW_)      // 1048576

__device__ int g_map[BHW_];  // zero-initialized at load; 0 = empty

// ---------------------------------------------------------------------------
// Kernel 1: scatter (pid+1) per pillar. atomicMax => highest pillar index
// wins == the reference's sequential last-write-wins. Coords (6.5 MB) left
// L2-cacheable for cross-replay residency.
__global__ void __launch_bounds__(512) k_scatter_idx(const int* __restrict__ coords, int P) {
    int p = blockIdx.x * blockDim.x + threadIdx.x;
    if (p >= P) return;
    int4 c = reinterpret_cast<const int4*>(coords)[p];  // [b, z, y, x]
    int b = c.x, y = c.z, x = c.w;
    if ((unsigned)y < H_ && (unsigned)x < W_) {
        atomicMax(&g_map[(b * H_ + y) * W_ + x], p + 1);
    }
}

// ---------------------------------------------------------------------------
// Kernel 2: gather + self-clean. One thread per BEV cell owns all 64
// channels: 16x float4 contiguous feature-row read (L2-cacheable), 64
// strided channel stores coalesced across the warp in w (streaming).
__global__ void __launch_bounds__(256) k_gather(const float* __restrict__ feat,
                                                float* __restrict__ out) {
    int s = blockIdx.x * blockDim.x + threadIdx.x;   // 0 .. BHW_-1
    int b  = s >> 18;            // / HW_
    int sp = s & (HW_ - 1);      // within-batch spatial index

    int v = g_map[s];

    float4 r[16];
    if (v > 0) {
        g_map[s] = 0;            // self-clean for next graph replay
        const float4* fp = reinterpret_cast<const float4*>(feat + (size_t)(v - 1) * C_);
#pragma unroll
        for (int i = 0; i < 16; i++) r[i] = fp[i];   // default policy: stay in L2
    } else {
#pragma unroll
        for (int i = 0; i < 16; i++) r[i] = make_float4(0.f, 0.f, 0.f, 0.f);
    }

    float* op = out + (size_t)b * (C_ * HW_) + sp;
#pragma unroll
    for (int i = 0; i < 16; i++) {
        __stcs(op + (size_t)(4 * i + 0) * HW_, r[i].x);
        __stcs(op + (size_t)(4 * i + 1) * HW_, r[i].y);
        __stcs(op + (size_t)(4 * i + 2) * HW_, r[i].z);
        __stcs(op + (size_t)(4 * i + 3) * HW_, r[i].w);
    }
}

// ---------------------------------------------------------------------------
extern "C" void kernel_launch(void* const* d_in, const int* in_sizes, int n_in,
                              void* d_out, int out_size) {
    const float* feat   = (const float*)d_in[0];   // [P, C] float32
    const int*   coords = (const int*)d_in[1];     // [P, 4] int32
    int P = in_sizes[1] / 4;

    k_scatter_idx<<<(P + 511) / 512, 512>>>(coords, P);
    k_gather<<<BHW_ / 256, 256>>>(feat, (float*)d_out);
}

// round 9
// speedup vs baseline: 1.5553x; 1.0702x over previous
#include <cuda_runtime.h>
#include <cstdint>

// PointPillars scatter, inverted as index-map + gather, with a PDL edge
// between the two kernels to hide the second launch's latency.
// B=4, C=64, H=512, W=512, P read from in_sizes.
//
// Init-free map: g_map holds (pid+1), 0 = empty. Zero-initialized at module
// load; gather self-cleans consumed cells so every graph replay starts from
// a clean map (gather -> next-replay scatter is ordered by the stream).
//
// Measured invariants (rounds 5-8): gather is ~57-60us at DRAM ~65%
// regardless of occupancy or cache policy; barriers between the random
// feature reads and the stores are catastrophic (round 7). So: no smem, no
// __syncthreads, __ldcs on the one-shot feature stream, __stcs on the
// 256 MB output stream.
#define B_ 4
#define C_ 64
#define H_ 512
#define W_ 512
#define HW_ (H_ * W_)        // 262144 = 2^18
#define BHW_ (B_ * HW_)      // 1048576

__device__ int g_map[BHW_];  // zero-initialized at load; 0 = empty

// ---------------------------------------------------------------------------
// Kernel 1: scatter (pid+1) per pillar. atomicMax => highest pillar index
// wins == the reference's sequential last-write-wins. Triggers the PDL
// dependent (gather) once its own work is issued.
__global__ void __launch_bounds__(512) k_scatter_idx(const int* __restrict__ coords, int P) {
    int p = blockIdx.x * blockDim.x + threadIdx.x;
    if (p < P) {
        int4 c = __ldcs(reinterpret_cast<const int4*>(coords) + p);  // [b,z,y,x]
        int b = c.x, y = c.z, x = c.w;
        if ((unsigned)y < H_ && (unsigned)x < W_) {
            atomicMax(&g_map[(b * H_ + y) * W_ + x], p + 1);
        }
    }
    cudaTriggerProgrammaticLaunchCompletion();
}

// ---------------------------------------------------------------------------
// Kernel 2: gather + self-clean. One thread per BEV cell owns all 64
// channels: 16x float4 contiguous feature-row read (streaming), 64 strided
// channel stores coalesced across the warp in w (streaming). Launched with
// PDL: waits for the scatter grid only at the map read.
__global__ void __launch_bounds__(256) k_gather(const float* __restrict__ feat,
                                                float* __restrict__ out) {
    int s = blockIdx.x * blockDim.x + threadIdx.x;   // 0 .. BHW_-1
    int b  = s >> 18;            // / HW_
    int sp = s & (HW_ - 1);      // within-batch spatial index

    cudaGridDependencySynchronize();   // scatter grid fully complete

    int v = g_map[s];

    float4 r[16];
    if (v > 0) {
        g_map[s] = 0;            // self-clean for next graph replay
        const float4* fp = reinterpret_cast<const float4*>(feat + (size_t)(v - 1) * C_);
#pragma unroll
        for (int i = 0; i < 16; i++) r[i] = __ldcs(fp + i);
    } else {
#pragma unroll
        for (int i = 0; i < 16; i++) r[i] = make_float4(0.f, 0.f, 0.f, 0.f);
    }

    float* op = out + (size_t)b * (C_ * HW_) + sp;
#pragma unroll
    for (int i = 0; i < 16; i++) {
        __stcs(op + (size_t)(4 * i + 0) * HW_, r[i].x);
        __stcs(op + (size_t)(4 * i + 1) * HW_, r[i].y);
        __stcs(op + (size_t)(4 * i + 2) * HW_, r[i].z);
        __stcs(op + (size_t)(4 * i + 3) * HW_, r[i].w);
    }
}

// ---------------------------------------------------------------------------
extern "C" void kernel_launch(void* const* d_in, const int* in_sizes, int n_in,
                              void* d_out, int out_size) {
    const float* feat   = (const float*)d_in[0];   // [P, C] float32
    const int*   coords = (const int*)d_in[1];     // [P, 4] int32
    int P = in_sizes[1] / 4;

    k_scatter_idx<<<(P + 511) / 512, 512>>>(coords, P);

    // Gather with programmatic dependent launch on the scatter.
    cudaLaunchConfig_t cfg = {};
    cfg.gridDim  = dim3(BHW_ / 256);
    cfg.blockDim = dim3(256);
    cfg.stream   = 0;  // capture stream
    cudaLaunchAttribute attr[1];
    attr[0].id = cudaLaunchAttributeProgrammaticStreamSerialization;
    attr[0].val.programmaticStreamSerializationAllowed = 1;
    cfg.attrs    = attr;
    cfg.numAttrs = 1;
    cudaLaunchKernelEx(&cfg, k_gather, feat, (float*)d_out);
}